// round 4
// baseline (speedup 1.0000x reference)
#include <cuda_runtime.h>
#include <cstdint>
#include <cstddef>

// ---------------------------------------------------------------------------
// Paged causal GQA attention (fp32 SIMT, f32x2-packed FMA), sm_103a.
// B=32, Q=16, Hq=32, Hkv=8 (G=4), D=128, page=16, pages/seq=256 -> K=4096.
// Grid: 256 CTAs = (b, hkv); 256 threads (2 warps/SMSP).
// Flash online softmax; KV streamed in 64-key tiles, double-buffered cp.async
// with SPLIT K/V commit groups: K-refill issues mid-tile (after the barrier
// that retires all K reads), overlapping the PV phase.
// Per thread: 4 query rows (r = ty*4+i), score cols 2*tx(+1)+32j.
// ---------------------------------------------------------------------------

typedef unsigned long long u64;
typedef unsigned int u32;

namespace {
constexpr int kB   = 32;
constexpr int kQ   = 16;
constexpr int kHQ  = 32;
constexpr int kHKV = 8;
constexpr int kG   = 4;
constexpr int kD   = 128;
constexpr int kPPS = 256;                 // pages per sequence
constexpr int kNT  = 64;                  // keys per tile
constexpr int kNTiles = 4096 / kNT;       // 64
constexpr int SK = 66;                    // Ks row stride: even (8B-aligned f32x2
                                          // reads), conflict-free read banks
constexpr int SP = 68;                    // Ps row stride

// shared memory layout (float offsets)
constexpr int QS_OFF = 0;                        // Qs[d][64], transposed+prescaled
constexpr int KTILE  = kD * SK;                  // 8448 floats
constexpr int KS_OFF = QS_OFF + kD * 64;         // two K buffers
constexpr int VTILE  = kNT * kD;                 // 8192 floats
constexpr int VS_OFF = KS_OFF + 2 * KTILE;       // two V buffers
constexpr int PS_OFF = VS_OFF + 2 * VTILE;       // Ps[k][r], 64 x SP
constexpr int PT_OFF = PS_OFF + kNT * SP;        // page table (256 ints)
constexpr int SMEM_FLOATS = PT_OFF + kPPS;
constexpr int SMEM_BYTES  = SMEM_FLOATS * 4;     // 184320 B -> 1 CTA/SM
}  // namespace

// ---- f32x2 packed math (FFMA2 path reachable only via PTX) ----------------
__device__ __forceinline__ u64 ffma2(u64 a, u64 b, u64 c) {
    u64 d;
    asm("fma.rn.f32x2 %0, %1, %2, %3;" : "=l"(d) : "l"(a), "l"(b), "l"(c));
    return d;
}
__device__ __forceinline__ u64 fmul2(u64 a, u64 b) {
    u64 d;
    asm("mul.rn.f32x2 %0, %1, %2;" : "=l"(d) : "l"(a), "l"(b));
    return d;
}
__device__ __forceinline__ u64 bcast2(float x) {
    u64 r;
    asm("mov.b64 %0, {%1, %1};" : "=l"(r) : "f"(x));
    return r;
}
__device__ __forceinline__ float2 unpk(u64 v) {
    float2 f;
    asm("mov.b64 {%0, %1}, %2;" : "=f"(f.x), "=f"(f.y) : "l"(v));
    return f;
}
__device__ __forceinline__ u64 pack2(float x, float y) {
    u64 r;
    asm("mov.b64 %0, {%1, %2};" : "=l"(r) : "f"(x), "f"(y));
    return r;
}
__device__ __forceinline__ float exp2a(float x) {
    float y;
    asm("ex2.approx.ftz.f32 %0, %1;" : "=f"(y) : "f"(x));
    return y;
}

// ---- cp.async --------------------------------------------------------------
__device__ __forceinline__ void cpa4(u32 dst, const void* src) {
    asm volatile("cp.async.ca.shared.global [%0], [%1], 4;" :: "r"(dst), "l"(src));
}
__device__ __forceinline__ void cpa16(u32 dst, const void* src) {
    asm volatile("cp.async.cg.shared.global [%0], [%1], 16;" :: "r"(dst), "l"(src));
}
#define CP_COMMIT() asm volatile("cp.async.commit_group;")
#define CP_WAIT2()  asm volatile("cp.async.wait_group 2;")

__global__ void __launch_bounds__(256, 1)
gqa_paged_kernel(const float* __restrict__ qry,
                 const float* __restrict__ kc,
                 const float* __restrict__ vc,
                 const int*   __restrict__ ptab,
                 float*       __restrict__ out)
{
    extern __shared__ float sm[];
    const int t  = threadIdx.x;
    const int tx = t & 15;          // 16 column groups
    const int ty = t >> 4;          // 16 row groups; q = ty
    const int b  = blockIdx.x >> 3;
    const int h  = blockIdx.x & 7;

    float* Qs = sm + QS_OFF;
    float* Ks = sm + KS_OFF;
    float* Vs = sm + VS_OFF;
    float* Ps = sm + PS_OFF;
    int*   pts = reinterpret_cast<int*>(sm + PT_OFF);

    pts[t] = ptab[b * kPPS + t];
    __syncthreads();

    const u32 smb  = (u32)__cvta_generic_to_shared(sm);
    const u32 ks_u = smb + KS_OFF * 4;
    const u32 vs_u = smb + VS_OFF * 4;

    // K tile -> smem transposed [d][k]; own commit group.
    auto load_K = [&](int it, int buf) {
        const u32 kd = ks_u + (u32)buf * (KTILE * 4);
        const int d  = t & 127;
        const int sh = (t >> 7) * 32;          // 0 or 32
        const int p0 = pts[it * 4 + 0], p1 = pts[it * 4 + 1];
        const int p2 = pts[it * 4 + 2], p3 = pts[it * 4 + 3];
        const int pg[4] = {p0, p1, p2, p3};
        #pragma unroll
        for (int u = 0; u < 32; u++) {
            const int s = sh + u;              // key in tile
            const float* src = kc + (size_t)pg[s >> 4] * 16384
                                  + (s & 15) * 1024 + h * 128 + d;
            cpa4(kd + (u32)(d * SK + s) * 4, src);
        }
        CP_COMMIT();
    };
    // V tile -> smem natural [k][d]; own commit group.
    auto load_V = [&](int it, int buf) {
        const u32 vd = vs_u + (u32)buf * (VTILE * 4);
        const int w = t >> 5, d4 = t & 31;
        #pragma unroll
        for (int s = 0; s < 8; s++) {
            const int kk = s * 8 + w;
            const float* src = vc + (size_t)pts[it * 4 + (kk >> 4)] * 16384
                                  + (kk & 15) * 1024 + h * 128 + d4 * 4;
            cpa16(vd + (u32)(kk * 128 + d4 * 4) * 4, src);
        }
        CP_COMMIT();
    };

    load_K(0, 0); load_V(0, 0);
    load_K(1, 1); load_V(1, 1);

    // Q -> smem transposed [d][row], prescaled by (1/sqrt(D)) * log2(e).
    {
        const int row = t >> 2, dh = (t & 3) * 32;   // row = q*4+g
        const int q = row >> 2, g = row & 3;
        const float4* qsrc = reinterpret_cast<const float4*>(
            qry + ((size_t)(b * kQ + q) * kHQ + h * kG + g) * kD + dh);
        const float qsc = 0.08838834764831845f * 1.4426950408889634f;
        #pragma unroll
        for (int u = 0; u < 8; u++) {
            float4 v = qsrc[u];
            const int d = dh + u * 4;
            Qs[(d + 0) * 64 + row] = v.x * qsc;
            Qs[(d + 1) * 64 + row] = v.y * qsc;
            Qs[(d + 2) * 64 + row] = v.z * qsc;
            Qs[(d + 3) * 64 + row] = v.w * qsc;
        }
    }

    // Per-thread state: rows r = ty*4 + i (q = ty, g = i),
    // output d-pairs at 2*tx + 32*j, j = 0..3.
    u64   o[4][4];
    float m[4], l[4];
    #pragma unroll
    for (int i = 0; i < 4; i++) {
        o[i][0] = o[i][1] = o[i][2] = o[i][3] = 0ull;
        m[i] = -1e30f;
        l[i] = 0.0f;
    }

    for (int it = 0; it < kNTiles; it++) {
        const int buf = it & 1;
        CP_WAIT2();         // newest 2 groups = next tile's K,V; tile `it` done
        __syncthreads();    // tile data visible; prev-iter Ps reads complete

        // ---- QK ----------------------------------------------------------
        u64 c[4][2];
        #pragma unroll
        for (int i = 0; i < 4; i++) c[i][0] = c[i][1] = 0ull;

        const float* Kb = Ks + buf * KTILE;
        #pragma unroll 4
        for (int d = 0; d < 128; d++) {
            float4 qa = *reinterpret_cast<const float4*>(Qs + d * 64 + ty * 4);
            u64 k0 = *reinterpret_cast<const u64*>(Kb + d * SK + tx * 2);
            u64 k1 = *reinterpret_cast<const u64*>(Kb + d * SK + tx * 2 + 32);
            const float qs_[4] = {qa.x, qa.y, qa.z, qa.w};
            #pragma unroll
            for (int i = 0; i < 4; i++) {
                u64 qq = bcast2(qs_[i]);
                c[i][0] = ffma2(qq, k0, c[i][0]);
                c[i][1] = ffma2(qq, k1, c[i][1]);
            }
        }

        // ---- causal mask (only last tile masks) --------------------------
        if (it == kNTiles - 1) {
            #pragma unroll
            for (int i = 0; i < 4; i++) {
                const int lim = 48 + ty;          // key-in-tile <= 48 + q
                #pragma unroll
                for (int j = 0; j < 2; j++) {
                    float2 v = unpk(c[i][j]);
                    const int k0i = 2 * tx + 32 * j;
                    if (k0i     > lim) v.x = -1e30f;
                    if (k0i + 1 > lim) v.y = -1e30f;
                    c[i][j] = pack2(v.x, v.y);
                }
            }
        }

        // ---- online softmax (base-2; Q prescaled by log2e) ---------------
        #pragma unroll
        for (int i = 0; i < 4; i++) {
            float2 a  = unpk(c[i][0]);
            float2 bb = unpk(c[i][1]);
            float mt = fmaxf(fmaxf(a.x, a.y), fmaxf(bb.x, bb.y));
            mt = fmaxf(mt, __shfl_xor_sync(0xffffffffu, mt, 1, 16));
            mt = fmaxf(mt, __shfl_xor_sync(0xffffffffu, mt, 2, 16));
            mt = fmaxf(mt, __shfl_xor_sync(0xffffffffu, mt, 4, 16));
            mt = fmaxf(mt, __shfl_xor_sync(0xffffffffu, mt, 8, 16));
            const float mn    = fmaxf(m[i], mt);
            const float alpha = exp2a(m[i] - mn);
            m[i] = mn;
            const float p0 = exp2a(a.x - mn),  p1 = exp2a(a.y - mn);
            const float p2 = exp2a(bb.x - mn), p3 = exp2a(bb.y - mn);
            float s = (p0 + p1) + (p2 + p3);
            s += __shfl_xor_sync(0xffffffffu, s, 1, 16);
            s += __shfl_xor_sync(0xffffffffu, s, 2, 16);
            s += __shfl_xor_sync(0xffffffffu, s, 4, 16);
            s += __shfl_xor_sync(0xffffffffu, s, 8, 16);
            l[i] = l[i] * alpha + s;
            const u64 av = bcast2(alpha);
            o[i][0] = fmul2(o[i][0], av);
            o[i][1] = fmul2(o[i][1], av);
            o[i][2] = fmul2(o[i][2], av);
            o[i][3] = fmul2(o[i][3], av);
            const int r = ty * 4 + i;
            Ps[(2 * tx + 0)  * SP + r] = p0;
            Ps[(2 * tx + 1)  * SP + r] = p1;
            Ps[(2 * tx + 32) * SP + r] = p2;
            Ps[(2 * tx + 33) * SP + r] = p3;
        }
        __syncthreads();    // Ps visible; ALL Ks[buf] reads retired

        // K-refill of this buffer can start now, overlapping PV.
        if (it + 2 < kNTiles) load_K(it + 2, buf);
        else                  CP_COMMIT();       // empty group keeps counts valid

        // ---- PV: o[i][j] += P[r][k] * V[k][d-pair] -----------------------
        const float* Vb = Vs + buf * VTILE;
        #pragma unroll 2
        for (int k = 0; k < kNT; k++) {
            float4 pa = *reinterpret_cast<const float4*>(Ps + k * SP + ty * 4);
            u64 v0 = *reinterpret_cast<const u64*>(Vb + k * 128 + 2 * tx);
            u64 v1 = *reinterpret_cast<const u64*>(Vb + k * 128 + 2 * tx + 32);
            u64 v2 = *reinterpret_cast<const u64*>(Vb + k * 128 + 2 * tx + 64);
            u64 v3 = *reinterpret_cast<const u64*>(Vb + k * 128 + 2 * tx + 96);
            const float ps_[4] = {pa.x, pa.y, pa.z, pa.w};
            #pragma unroll
            for (int i = 0; i < 4; i++) {
                u64 pp = bcast2(ps_[i]);
                o[i][0] = ffma2(pp, v0, o[i][0]);
                o[i][1] = ffma2(pp, v1, o[i][1]);
                o[i][2] = ffma2(pp, v2, o[i][2]);
                o[i][3] = ffma2(pp, v3, o[i][3]);
            }
        }
        __syncthreads();    // all Vs[buf] reads retired before V-refill

        if (it + 2 < kNTiles) load_V(it + 2, buf);
        else                  CP_COMMIT();       // empty group
    }

    // ---- epilogue: normalize and store (coalesced 8B stores) --------------
    #pragma unroll
    for (int i = 0; i < 4; i++) {
        const int q = ty, g = i;
        const float inv = 1.0f / l[i];
        const u64 iv = bcast2(inv);
        float* orow = out + (size_t)(b * kQ + q) * (kHQ * kD) + (h * kG + g) * kD;
        #pragma unroll
        for (int j = 0; j < 4; j++) {
            float2 v = unpk(fmul2(o[i][j], iv));
            *reinterpret_cast<float2*>(orow + 2 * tx + 32 * j) = v;
        }
    }
}

extern "C" void kernel_launch(void* const* d_in, const int* in_sizes, int n_in,
                              void* d_out, int out_size) {
    (void)in_sizes; (void)n_in; (void)out_size;
    const float* qry  = (const float*)d_in[0];
    const float* kc   = (const float*)d_in[1];
    const float* vc   = (const float*)d_in[2];
    const int*   ptab = (const int*)d_in[3];
    float*       out  = (float*)d_out;

    cudaFuncSetAttribute(gqa_paged_kernel,
                         cudaFuncAttributeMaxDynamicSharedMemorySize,
                         SMEM_BYTES);
    gqa_paged_kernel<<<kB * kHKV, 256, SMEM_BYTES>>>(qry, kc, vc, ptab, out);
}

// round 10
// speedup vs baseline: 1.0154x; 1.0154x over previous
#include <cuda_runtime.h>
#include <cstdint>
#include <cstddef>

// ---------------------------------------------------------------------------
// Paged causal GQA attention (fp32 SIMT, f32x2-packed FMA), sm_103a.
// 32-key tiles -> smem 107.5KB -> 2 CTAs/SM (16 warps) for latency hiding,
// and 256 CTAs fit in ONE wave (296 slots).
// Grid: 256 CTAs = (b, hkv); 256 threads; __launch_bounds__(256,2).
// Per thread: 4 query rows (r = ty*4+i), 2 score cols (2tx, 2tx+1),
// 8 output floats (4 f32x2 d-pairs at 2tx+32j).
// ---------------------------------------------------------------------------

typedef unsigned long long u64;
typedef unsigned int u32;

namespace {
constexpr int kB   = 32;
constexpr int kQ   = 16;
constexpr int kHQ  = 32;
constexpr int kHKV = 8;
constexpr int kG   = 4;
constexpr int kD   = 128;
constexpr int kPPS = 256;                 // pages per sequence
constexpr int kNT  = 32;                  // keys per tile
constexpr int kNTiles = 4096 / kNT;       // 128
constexpr int SK = 34;                    // Ks row stride (even for 8B loads;
                                          // write side 2-way conflict, read clean)
constexpr int SP = 68;                    // Ps row stride

// shared memory layout (float offsets)
constexpr int QS_OFF = 0;                        // Qs[d][64], transposed+prescaled
constexpr int KTILE  = kD * SK;                  // 4352 floats
constexpr int KS_OFF = QS_OFF + kD * 64;         // two K buffers
constexpr int VTILE  = kNT * kD;                 // 4096 floats
constexpr int VS_OFF = KS_OFF + 2 * KTILE;       // two V buffers
constexpr int PS_OFF = VS_OFF + 2 * VTILE;       // Ps[k][r], 32 x SP
constexpr int PT_OFF = PS_OFF + kNT * SP;        // page table (256 ints)
constexpr int SMEM_FLOATS = PT_OFF + kPPS;
constexpr int SMEM_BYTES  = SMEM_FLOATS * 4;     // 110080 B -> 2 CTAs/SM
}  // namespace

// ---- f32x2 packed math (FFMA2 path reachable only via PTX) ----------------
__device__ __forceinline__ u64 ffma2(u64 a, u64 b, u64 c) {
    u64 d;
    asm("fma.rn.f32x2 %0, %1, %2, %3;" : "=l"(d) : "l"(a), "l"(b), "l"(c));
    return d;
}
__device__ __forceinline__ u64 fmul2(u64 a, u64 b) {
    u64 d;
    asm("mul.rn.f32x2 %0, %1, %2;" : "=l"(d) : "l"(a), "l"(b));
    return d;
}
__device__ __forceinline__ u64 bcast2(float x) {
    u64 r;
    asm("mov.b64 %0, {%1, %1};" : "=l"(r) : "f"(x));
    return r;
}
__device__ __forceinline__ float2 unpk(u64 v) {
    float2 f;
    asm("mov.b64 {%0, %1}, %2;" : "=f"(f.x), "=f"(f.y) : "l"(v));
    return f;
}
__device__ __forceinline__ float exp2a(float x) {
    float y;
    asm("ex2.approx.ftz.f32 %0, %1;" : "=f"(y) : "f"(x));
    return y;
}

// ---- cp.async --------------------------------------------------------------
__device__ __forceinline__ void cpa4(u32 dst, const void* src) {
    asm volatile("cp.async.ca.shared.global [%0], [%1], 4;" :: "r"(dst), "l"(src));
}
__device__ __forceinline__ void cpa16(u32 dst, const void* src) {
    asm volatile("cp.async.cg.shared.global [%0], [%1], 16;" :: "r"(dst), "l"(src));
}
#define CP_COMMIT() asm volatile("cp.async.commit_group;")
#define CP_WAIT2()  asm volatile("cp.async.wait_group 2;")

__global__ void __launch_bounds__(256, 2)
gqa_paged_kernel(const float* __restrict__ qry,
                 const float* __restrict__ kc,
                 const float* __restrict__ vc,
                 const int*   __restrict__ ptab,
                 float*       __restrict__ out)
{
    extern __shared__ float sm[];
    const int t  = threadIdx.x;
    const int tx = t & 15;          // 16 column groups (cols 2tx, 2tx+1)
    const int ty = t >> 4;          // 16 row groups; q = ty
    const int b  = blockIdx.x >> 3;
    const int h  = blockIdx.x & 7;

    float* Qs = sm + QS_OFF;
    float* Ks = sm + KS_OFF;
    float* Vs = sm + VS_OFF;
    float* Ps = sm + PS_OFF;
    int*   pts = reinterpret_cast<int*>(sm + PT_OFF);

    pts[t] = ptab[b * kPPS + t];
    __syncthreads();

    const u32 smb  = (u32)__cvta_generic_to_shared(sm);
    const u32 ks_u = smb + KS_OFF * 4;
    const u32 vs_u = smb + VS_OFF * 4;

    // K tile (32 keys) -> smem transposed [d][k]; own commit group.
    // Tile `it` covers keys it*32..it*32+31 -> pages it*2, it*2+1.
    auto load_K = [&](int it, int buf) {
        const u32 kd = ks_u + (u32)buf * (KTILE * 4);
        const int d  = t & 127;
        const int ph = t >> 7;                 // 0 or 1 (which page half)
        const float* base = kc + (size_t)pts[it * 2 + ph] * 16384 + h * 128 + d;
        const int s0 = ph * 16;
        #pragma unroll
        for (int u = 0; u < 16; u++) {
            cpa4(kd + (u32)(d * SK + s0 + u) * 4, base + u * 1024);
        }
        CP_COMMIT();
    };
    // V tile -> smem natural [k][d]; own commit group.
    auto load_V = [&](int it, int buf) {
        const u32 vd = vs_u + (u32)buf * (VTILE * 4);
        const int w = t >> 5, d4 = t & 31;
        #pragma unroll
        for (int s = 0; s < 4; s++) {
            const int kk = s * 8 + w;
            const float* src = vc + (size_t)pts[it * 2 + (kk >> 4)] * 16384
                                  + (kk & 15) * 1024 + h * 128 + d4 * 4;
            cpa16(vd + (u32)(kk * 128 + d4 * 4) * 4, src);
        }
        CP_COMMIT();
    };

    load_K(0, 0); load_V(0, 0);
    load_K(1, 1); load_V(1, 1);

    // Q -> smem transposed [d][row], prescaled by (1/sqrt(D)) * log2(e).
    {
        const int row = t >> 2, dh = (t & 3) * 32;   // row = q*4+g
        const int q = row >> 2, g = row & 3;
        const float4* qsrc = reinterpret_cast<const float4*>(
            qry + ((size_t)(b * kQ + q) * kHQ + h * kG + g) * kD + dh);
        const float qsc = 0.08838834764831845f * 1.4426950408889634f;
        #pragma unroll
        for (int u = 0; u < 8; u++) {
            float4 v = qsrc[u];
            const int d = dh + u * 4;
            Qs[(d + 0) * 64 + row] = v.x * qsc;
            Qs[(d + 1) * 64 + row] = v.y * qsc;
            Qs[(d + 2) * 64 + row] = v.z * qsc;
            Qs[(d + 3) * 64 + row] = v.w * qsc;
        }
    }

    // Per-thread state.
    u64   o[4][4];
    float m[4], l[4];
    #pragma unroll
    for (int i = 0; i < 4; i++) {
        o[i][0] = o[i][1] = o[i][2] = o[i][3] = 0ull;
        m[i] = -1e30f;
        l[i] = 0.0f;
    }

    for (int it = 0; it < kNTiles; it++) {
        const int buf = it & 1;
        CP_WAIT2();         // 2 newest groups = next tile's K,V; tile `it` ready
        __syncthreads();    // visible to all; prev-iter Ps reads retired

        // ---- QK: scores for rows ty*4+i, cols 2tx(+1) --------------------
        u64 c[4];
        c[0] = c[1] = c[2] = c[3] = 0ull;

        const float* Kb = Ks + buf * KTILE;
        #pragma unroll 8
        for (int d = 0; d < 128; d++) {
            float4 qa = *reinterpret_cast<const float4*>(Qs + d * 64 + ty * 4);
            u64 k0 = *reinterpret_cast<const u64*>(Kb + d * SK + tx * 2);
            c[0] = ffma2(bcast2(qa.x), k0, c[0]);
            c[1] = ffma2(bcast2(qa.y), k0, c[1]);
            c[2] = ffma2(bcast2(qa.z), k0, c[2]);
            c[3] = ffma2(bcast2(qa.w), k0, c[3]);
        }

        // ---- causal mask (only last tile masks) --------------------------
        // Last tile keys: 4064+s; qpos = 4080+q -> mask s <= 16 + q (q = ty).
        if (it == kNTiles - 1) {
            const int lim = 16 + ty;
            #pragma unroll
            for (int i = 0; i < 4; i++) {
                float2 v = unpk(c[i]);
                if (2 * tx     > lim) v.x = -1e30f;
                if (2 * tx + 1 > lim) v.y = -1e30f;
                asm("mov.b64 %0, {%1, %2};" : "=l"(c[i]) : "f"(v.x), "f"(v.y));
            }
        }

        // ---- online softmax (base-2; Q prescaled by log2e) ---------------
        #pragma unroll
        for (int i = 0; i < 4; i++) {
            float2 a = unpk(c[i]);
            float mt = fmaxf(a.x, a.y);
            mt = fmaxf(mt, __shfl_xor_sync(0xffffffffu, mt, 1, 16));
            mt = fmaxf(mt, __shfl_xor_sync(0xffffffffu, mt, 2, 16));
            mt = fmaxf(mt, __shfl_xor_sync(0xffffffffu, mt, 4, 16));
            mt = fmaxf(mt, __shfl_xor_sync(0xffffffffu, mt, 8, 16));
            const float mn    = fmaxf(m[i], mt);
            const float alpha = exp2a(m[i] - mn);
            m[i] = mn;
            const float p0 = exp2a(a.x - mn), p1 = exp2a(a.y - mn);
            float s = p0 + p1;
            s += __shfl_xor_sync(0xffffffffu, s, 1, 16);
            s += __shfl_xor_sync(0xffffffffu, s, 2, 16);
            s += __shfl_xor_sync(0xffffffffu, s, 4, 16);
            s += __shfl_xor_sync(0xffffffffu, s, 8, 16);
            l[i] = l[i] * alpha + s;
            const u64 av = bcast2(alpha);
            o[i][0] = fmul2(o[i][0], av);
            o[i][1] = fmul2(o[i][1], av);
            o[i][2] = fmul2(o[i][2], av);
            o[i][3] = fmul2(o[i][3], av);
            const int r = ty * 4 + i;
            Ps[(2 * tx + 0) * SP + r] = p0;
            Ps[(2 * tx + 1) * SP + r] = p1;
        }
        __syncthreads();    // Ps visible; ALL Ks[buf] reads retired

        // K-refill of this buffer overlaps PV.
        if (it + 2 < kNTiles) load_K(it + 2, buf);
        else                  CP_COMMIT();       // keep group-count math valid

        // ---- PV: o[i][j] += P[r][k] * V[k][d-pair] -----------------------
        const float* Vb = Vs + buf * VTILE;
        #pragma unroll 2
        for (int k = 0; k < kNT; k++) {
            float4 pa = *reinterpret_cast<const float4*>(Ps + k * SP + ty * 4);
            u64 v0 = *reinterpret_cast<const u64*>(Vb + k * 128 + 2 * tx);
            u64 v1 = *reinterpret_cast<const u64*>(Vb + k * 128 + 2 * tx + 32);
            u64 v2 = *reinterpret_cast<const u64*>(Vb + k * 128 + 2 * tx + 64);
            u64 v3 = *reinterpret_cast<const u64*>(Vb + k * 128 + 2 * tx + 96);
            const float ps_[4] = {pa.x, pa.y, pa.z, pa.w};
            #pragma unroll
            for (int i = 0; i < 4; i++) {
                u64 pp = bcast2(ps_[i]);
                o[i][0] = ffma2(pp, v0, o[i][0]);
                o[i][1] = ffma2(pp, v1, o[i][1]);
                o[i][2] = ffma2(pp, v2, o[i][2]);
                o[i][3] = ffma2(pp, v3, o[i][3]);
            }
        }
        __syncthreads();    // all Vs[buf] reads retired before V-refill

        if (it + 2 < kNTiles) load_V(it + 2, buf);
        else                  CP_COMMIT();       // empty group
    }

    // ---- epilogue: normalize and store (coalesced 8B stores) --------------
    #pragma unroll
    for (int i = 0; i < 4; i++) {
        const int q = ty, g = i;
        const float inv = 1.0f / l[i];
        const u64 iv = bcast2(inv);
        float* orow = out + (size_t)(b * kQ + q) * (kHQ * kD) + (h * kG + g) * kD;
        #pragma unroll
        for (int j = 0; j < 4; j++) {
            float2 v = unpk(fmul2(o[i][j], iv));
            *reinterpret_cast<float2*>(orow + 2 * tx + 32 * j) = v;
        }
    }
}

extern "C" void kernel_launch(void* const* d_in, const int* in_sizes, int n_in,
                              void* d_out, int out_size) {
    (void)in_sizes; (void)n_in; (void)out_size;
    const float* qry  = (const float*)d_in[0];
    const float* kc   = (const float*)d_in[1];
    const float* vc   = (const float*)d_in[2];
    const int*   ptab = (const int*)d_in[3];
    float*       out  = (float*)d_out;

    cudaFuncSetAttribute(gqa_paged_kernel,
                         cudaFuncAttributeMaxDynamicSharedMemorySize,
                         SMEM_BYTES);
    gqa_paged_kernel<<<kB * kHKV, 256, SMEM_BYTES>>>(qry, kc, vc, ptab, out);
}